// round 17
// baseline (speedup 1.0000x reference)
#include <cuda_runtime.h>
#include <cuda_fp16.h>
#include <cstdint>

// Problem constants
#define SQ   2048
#define DIM  768
#define NH   12
#define DH   64
#define NB   2
#define BH   (NB*NH)   // 24

// fp16 scratch: [5][BH][S][DH]  (qr,qi,kr,ki,v)
__device__ __align__(16) __half g_hi[5u * BH * SQ * DH];
// fp16 copies of inputs
__device__ __align__(16) __half g_xhi[4096u * DIM];
__device__ __align__(16) __half g_whi[5u * DIM * DIM];

// ---------------------------------------------------------------------------
// helpers
// ---------------------------------------------------------------------------
__device__ __forceinline__ uint32_t sm_u32(const void* p) {
    return (uint32_t)__cvta_generic_to_shared(p);
}
__device__ __forceinline__ void ldsm4(uint32_t* r, uint32_t a) {
    asm volatile("ldmatrix.sync.aligned.m8n8.x4.shared.b16 {%0,%1,%2,%3}, [%4];"
                 : "=r"(r[0]), "=r"(r[1]), "=r"(r[2]), "=r"(r[3]) : "r"(a));
}
__device__ __forceinline__ void ldsm4t(uint32_t* r, uint32_t a) {
    asm volatile("ldmatrix.sync.aligned.m8n8.x4.trans.shared.b16 {%0,%1,%2,%3}, [%4];"
                 : "=r"(r[0]), "=r"(r[1]), "=r"(r[2]), "=r"(r[3]) : "r"(a));
}
__device__ __forceinline__ void mma16816(float* c, const uint32_t* a,
                                         uint32_t b0, uint32_t b1) {
    asm volatile(
        "mma.sync.aligned.m16n8k16.row.col.f32.f16.f16.f32 "
        "{%0,%1,%2,%3},{%4,%5,%6,%7},{%8,%9},{%0,%1,%2,%3};"
        : "+f"(c[0]), "+f"(c[1]), "+f"(c[2]), "+f"(c[3])
        : "r"(a[0]), "r"(a[1]), "r"(a[2]), "r"(a[3]), "r"(b0), "r"(b1));
}
__device__ __forceinline__ void cpa16(uint32_t d, const void* s) {
    asm volatile("cp.async.cg.shared.global [%0], [%1], 16;" :: "r"(d), "l"(s));
}
__device__ __forceinline__ void cp_commit() { asm volatile("cp.async.commit_group;"); }
template<int N> __device__ __forceinline__ void cp_wait() {
    asm volatile("cp.async.wait_group %0;" :: "n"(N));
}
__device__ __forceinline__ float fsqrt_approx(float x) {
    float y;
    asm("sqrt.approx.ftz.f32 %0, %1;" : "=f"(y) : "f"(x));
    return y;
}

// ---------------------------------------------------------------------------
// Kernel 0: convert fp32 inputs -> fp16 (X and W, hi only)
// ---------------------------------------------------------------------------
__global__ __launch_bounds__(256) void split_kernel(
    const float* __restrict__ X,
    const float* __restrict__ W0, const float* __restrict__ W1,
    const float* __restrict__ W2, const float* __restrict__ W3,
    const float* __restrict__ W4)
{
    const int64_t NX4 = (int64_t)4096 * DIM / 4;
    const int64_t NW4 = (int64_t)DIM * DIM / 4;
    const int64_t total4 = NX4 + 5 * NW4;
    for (int64_t i4 = (int64_t)blockIdx.x * 256 + threadIdx.x;
         i4 < total4; i4 += (int64_t)gridDim.x * 256) {
        if (i4 < NX4) {
            float4 v = ((const float4*)X)[i4];
            __half2* dh = (__half2*)g_xhi + i4*2;
            dh[0] = __floats2half2_rn(v.x, v.y);
            dh[1] = __floats2half2_rn(v.z, v.w);
        } else {
            int64_t j = i4 - NX4;
            int ws = (int)(j / NW4);
            int64_t rem = j - (int64_t)ws * NW4;
            const float* Wp = (ws == 0) ? W0 : (ws == 1) ? W1 :
                              (ws == 2) ? W2 : (ws == 3) ? W3 : W4;
            float4 v = ((const float4*)Wp)[rem];
            __half2* dh = (__half2*)g_whi + j*2;
            dh[0] = __floats2half2_rn(v.x, v.y);
            dh[1] = __floats2half2_rn(v.z, v.w);
        }
    }
}

// ---------------------------------------------------------------------------
// Kernel 1: tensor-core projections.  C = Xhi @ Whi^T (single segment).
// CTA 128x128, 4 warps (2x2), warp tile 64x64 -> 2 CTAs/SM.
// cp.async double-buffered k64.
// ---------------------------------------------------------------------------
#define PKP  72
#define PSTG (2*128*PKP)   // halves per stage (Ahi,Bhi)
#define PTHR 128

__global__ __launch_bounds__(PTHR, 2) void proj_mma_kernel()
{
    extern __shared__ __half sp[];
    const int tid  = threadIdx.x;
    const int lane = tid & 31;
    const int w    = tid >> 5;          // 0..3
    const int bx      = blockIdx.x;
    const int which   = bx / 6;
    const int colBase = (bx % 6) * 128;
    const int rowBase = blockIdx.y * 128;

    const __half* Ahi = g_xhi;
    const __half* Bhi = g_whi + (size_t)which * DIM * DIM;

    auto load_stage = [&](int s, int k0) {
        #pragma unroll
        for (int it = 0; it < 16; it++) {
            int idx = tid + it*PTHR;         // < 2048
            int arr = idx >> 10;             // 0..1
            int rem = idx & 1023;
            int row = rem >> 3;
            int c8  = (rem & 7) * 8;
            const __half* gsrc = (arr == 0)
                ? Ahi + (size_t)(rowBase + row)*DIM + k0 + c8
                : Bhi + (size_t)(colBase + row)*DIM + k0 + c8;
            cpa16(sm_u32(sp + s*PSTG + arr*128*PKP + row*PKP + c8), gsrc);
        }
    };

    float acc[4][8][4];
    #pragma unroll
    for (int mt = 0; mt < 4; mt++)
        #pragma unroll
        for (int nt = 0; nt < 8; nt++)
            #pragma unroll
            for (int j = 0; j < 4; j++) acc[mt][nt][j] = 0.f;

    const int r  = lane & 15, sg = lane >> 4;
    const int q8 = lane >> 3, rr = lane & 7;
    const int wRow = (w >> 1) * 64;
    const int wCol = (w & 1) * 64;

    load_stage(0, 0); cp_commit();

    #pragma unroll 1
    for (int it = 0; it < 12; it++) {
        if (it + 1 < 12) { load_stage((it+1) & 1, (it+1)*64); cp_commit(); cp_wait<1>(); }
        else             cp_wait<0>();
        __syncthreads();

        const __half* A0 = sp + (it & 1)*PSTG;
        const __half* B0 = A0 + 128*PKP;

        #pragma unroll
        for (int kc = 0; kc < 4; kc++) {
            uint32_t ah[4][4], bh[4][4];
            #pragma unroll
            for (int mt = 0; mt < 4; mt++)
                ldsm4(ah[mt], sm_u32(A0 + (wRow + mt*16 + r)*PKP + kc*16 + sg*8));
            #pragma unroll
            for (int np = 0; np < 4; np++) {
                int brow = (wCol + np*16 + (q8 >> 1)*8 + rr)*PKP + kc*16 + (q8 & 1)*8;
                ldsm4(bh[np], sm_u32(B0 + brow));
            }
            #pragma unroll
            for (int mt = 0; mt < 4; mt++)
                #pragma unroll
                for (int np = 0; np < 4; np++)
                    #pragma unroll
                    for (int tt = 0; tt < 2; tt++)
                        mma16816(acc[mt][np*2 + tt], ah[mt],
                                 bh[np][2*tt], bh[np][2*tt+1]);
        }
        __syncthreads();
    }

    // epilogue: write per-head fp16 scratch (half2 stores, d even)
    #pragma unroll
    for (int mt = 0; mt < 4; mt++)
        #pragma unroll
        for (int nt = 0; nt < 8; nt++)
            #pragma unroll
            for (int jh = 0; jh < 2; jh++) {
                int row = rowBase + wRow + mt*16 + (lane >> 2) + jh*8;
                int col = colBase + wCol + nt*8 + (lane & 3)*2;
                int b_ = row >> 11, s_ = row & (SQ - 1);
                int h  = col >> 6,  d  = col & 63;
                size_t off = (((size_t)which*BH + (b_*NH + h))*SQ + s_)*DH + d;
                *(__half2*)(g_hi + off) =
                    __floats2half2_rn(acc[mt][nt][jh*2 + 0], acc[mt][nt][jh*2 + 1]);
            }
}

// ---------------------------------------------------------------------------
// Kernel 2: tensor-core complex flash attention (fp16, 4-MMA scores,
// 32-key score/softmax/PV chunks to cut register pressure).
// CTA = 64 q-rows x one bh, 4 warps (128 thr) -> 3 CTAs/SM.
// ---------------------------------------------------------------------------
#define KPAD 72
#define KVSTG (3*64*KPAD)   // halves per KV stage
#define ATHR 128

__global__ __launch_bounds__(ATHR, 3) void attn_kernel(float* __restrict__ out)
{
    extern __shared__ __half smh[];
    __half* qs  = smh;                  // 2 * 64 * KPAD (qr, qi)
    __half* kvs = smh + 2*64*KPAD;      // 2 stages * (kr,ki,v) 64*KPAD each

    const int tid  = threadIdx.x;
    const int lane = tid & 31;
    const int w    = tid >> 5;          // 0..3
    const int bh   = blockIdx.y;
    const int q0   = blockIdx.x * 64;

    const __half* Kr = g_hi + (size_t)(2*BH + bh) * SQ * DH;
    const __half* Ki = g_hi + (size_t)(3*BH + bh) * SQ * DH;
    const __half* Vv = g_hi + (size_t)(4*BH + bh) * SQ * DH;

    auto load_kv = [&](int s, int kt) {
        #pragma unroll
        for (int it = 0; it < 12; it++) {
            int idx = tid + it*ATHR;         // < 1536
            int arr = idx >> 9;              // 0..2
            int rem = idx & 511;
            int row = rem >> 3;
            int c8  = (rem & 7) * 8;
            const __half* gsrc = ((arr == 0) ? Kr : (arr == 1) ? Ki : Vv)
                                 + (size_t)(kt*64 + row)*DH + c8;
            cpa16(sm_u32(kvs + s*KVSTG + arr*64*KPAD + row*KPAD + c8), gsrc);
        }
    };

    // stage Q tiles (synchronous, one-time): 2 arrays x 64 rows x 8 uint4
    {
        const uint4* src[2] = {
            (const uint4*)(g_hi + ((size_t)(0*BH + bh) * SQ + q0) * DH),
            (const uint4*)(g_hi + ((size_t)(1*BH + bh) * SQ + q0) * DH)};
        #pragma unroll
        for (int it = 0; it < 8; it++) {
            int idx = tid + it*ATHR;         // < 1024
            int arr = idx >> 9;
            int rem = idx & 511;
            int row = rem >> 3;
            int c8  = rem & 7;
            *(uint4*)(qs + arr*64*KPAD + row*KPAD + c8*8) = src[arr][row*8 + c8];
        }
    }
    load_kv(0, 0); cp_commit();
    __syncthreads();

    uint32_t a_qr[4][4], a_qi[4][4];
    {
        int r = lane & 15, sg = lane >> 4;
        #pragma unroll
        for (int c = 0; c < 4; c++) {
            ldsm4(a_qr[c], sm_u32(qs + 0*64*KPAD + (w*16 + r)*KPAD + c*16 + sg*8));
            ldsm4(a_qi[c], sm_u32(qs + 1*64*KPAD + (w*16 + r)*KPAD + c*16 + sg*8));
        }
    }

    float o_acc[8][4];
    #pragma unroll
    for (int t = 0; t < 8; t++)
        #pragma unroll
        for (int j = 0; j < 4; j++) o_acc[t][j] = 0.f;
    float m_[2] = {-1e30f, -1e30f};
    float l_[2] = {0.f, 0.f};

    const int q8 = lane >> 3, rr = lane & 7;

    for (int kt = 0; kt < SQ/64; kt++) {
        if (kt + 1 < SQ/64) { load_kv((kt+1) & 1, kt+1); cp_commit(); cp_wait<1>(); }
        else                cp_wait<0>();
        __syncthreads();

        const __half* krp = kvs + (kt & 1)*KVSTG;
        const __half* kip = krp + 64*KPAD;
        const __half* vp  = krp + 2*64*KPAD;

        // process 64-key tile as two 32-key chunks (smaller register footprint)
        #pragma unroll
        for (int ch = 0; ch < 2; ch++) {
            // --- scores for 32 keys: sr = qr.kr + qi.ki ; si = qi.kr - qr.ki ---
            float sr[4][4], si[4][4];
            #pragma unroll
            for (int t = 0; t < 4; t++)
                #pragma unroll
                for (int j = 0; j < 4; j++) { sr[t][j] = 0.f; si[t][j] = 0.f; }

            #pragma unroll
            for (int c = 0; c < 4; c++) {
                #pragma unroll
                for (int tpl = 0; tpl < 2; tpl++) {
                    int tp  = ch*2 + tpl;
                    int row = tp*16 + (q8 >> 1)*8 + rr;
                    int col = c*16 + (q8 & 1)*8;
                    uint32_t br[4], bi[4];
                    ldsm4(br, sm_u32(krp + row*KPAD + col));
                    ldsm4(bi, sm_u32(kip + row*KPAD + col));
                    #pragma unroll
                    for (int tt = 0; tt < 2; tt++) {
                        int t = tpl*2 + tt;
                        mma16816(sr[t], a_qr[c], br[2*tt], br[2*tt+1]);
                        mma16816(sr[t], a_qi[c], bi[2*tt], bi[2*tt+1]);
                        mma16816(si[t], a_qi[c], br[2*tt], br[2*tt+1]);
                        mma16816(si[t], a_qr[c],
                                 bi[2*tt] ^ 0x80008000u, bi[2*tt+1] ^ 0x80008000u);
                    }
                }
            }

            // --- magnitude + online softmax over 32 keys; pack P frags ---
            uint32_t pah[2][4];
            #pragma unroll
            for (int h = 0; h < 2; h++) {
                float sv[8];
                float mx = m_[h];
                #pragma unroll
                for (int t = 0; t < 4; t++)
                    #pragma unroll
                    for (int j = 0; j < 2; j++) {
                        float a = sr[t][2*h + j], b = si[t][2*h + j];
                        float s = fsqrt_approx(fmaf(a, a, b*b)) * 0.125f;
                        sv[t*2 + j] = s;
                        mx = fmaxf(mx, s);
                    }
                mx = fmaxf(mx, __shfl_xor_sync(0xffffffffu, mx, 1));
                mx = fmaxf(mx, __shfl_xor_sync(0xffffffffu, mx, 2));
                float corr = __expf(m_[h] - mx);
                float sum = 0.f;
                #pragma unroll
                for (int t = 0; t < 4; t++) {
                    float p0 = __expf(sv[2*t]   - mx);
                    float p1 = __expf(sv[2*t+1] - mx);
                    sum += p0 + p1;
                    __half2 hh = __floats2half2_rn(p0, p1);
                    pah[t >> 1][(t & 1)*2 + h] = *reinterpret_cast<uint32_t*>(&hh);
                }
                sum += __shfl_xor_sync(0xffffffffu, sum, 1);
                sum += __shfl_xor_sync(0xffffffffu, sum, 2);
                l_[h] = l_[h]*corr + sum;
                m_[h] = mx;
                #pragma unroll
                for (int t = 0; t < 8; t++) {
                    o_acc[t][2*h]   *= corr;
                    o_acc[t][2*h+1] *= corr;
                }
            }

            // --- O += P(16x32) @ V(32x64) for this chunk ---
            #pragma unroll
            for (int c2 = 0; c2 < 2; c2++) {
                int ck = ch*2 + c2;
                #pragma unroll
                for (int tp = 0; tp < 4; tp++) {
                    int row = ck*16 + (q8 & 1)*8 + rr;
                    int col = tp*16 + (q8 >> 1)*8;
                    uint32_t bv[4];
                    ldsm4t(bv, sm_u32(vp + row*KPAD + col));
                    mma16816(o_acc[2*tp],     pah[c2], bv[0], bv[1]);
                    mma16816(o_acc[2*tp + 1], pah[c2], bv[2], bv[3]);
                }
            }
        }
        __syncthreads();
    }

    // epilogue
    const int b_ = bh / NH, hd = bh % NH;
    const int g  = lane >> 2, nj = (lane & 3)*2;
    #pragma unroll
    for (int h = 0; h < 2; h++) {
        float inv = 1.0f / l_[h];
        int row = q0 + w*16 + g + h*8;
        float* orow = out + (size_t)(b_*SQ + row)*DIM + hd*DH;
        #pragma unroll
        for (int t = 0; t < 8; t++) {
            float2 v2 = make_float2(o_acc[t][2*h]*inv, o_acc[t][2*h+1]*inv);
            *(float2*)(orow + t*8 + nj) = v2;
        }
    }
}

// ---------------------------------------------------------------------------
extern "C" void kernel_launch(void* const* d_in, const int* in_sizes, int n_in,
                              void* d_out, int out_size)
{
    const float* X   = (const float*)d_in[0];
    const float* Wqr = (const float*)d_in[1];
    const float* Wqi = (const float*)d_in[2];
    const float* Wkr = (const float*)d_in[3];
    const float* Wki = (const float*)d_in[4];
    const float* Wv  = (const float*)d_in[5];
    float* out = (float*)d_out;

    const int proj_smem = 2 * PSTG * (int)sizeof(__half);                // 73728
    const int attn_smem = (2*64*KPAD + 2*KVSTG) * (int)sizeof(__half);   // 73728
    cudaFuncSetAttribute(proj_mma_kernel, cudaFuncAttributeMaxDynamicSharedMemorySize, proj_smem);
    cudaFuncSetAttribute(attn_kernel, cudaFuncAttributeMaxDynamicSharedMemorySize, attn_smem);

    split_kernel<<<1024, 256>>>(X, Wqr, Wqi, Wkr, Wki, Wv);
    proj_mma_kernel<<<dim3(30, 32), PTHR, proj_smem>>>();
    attn_kernel<<<dim3(SQ/64, BH), ATHR, attn_smem>>>(out);
}